// round 9
// baseline (speedup 1.0000x reference)
#include <cuda_runtime.h>

#define IN_DIM 256
#define FEAT   33152      // 256 + (256 + 256*256)/2 = 259 * 128
#define NB     8          // batch
#define NROWS  8192       // NHEAD * S * D_MODEL
#define KC     512        // k-floats per pipeline chunk (2 KB per row per bulk op)
#define NCH    65         // 64 full chunks + tail of 384
#define OUTF   64

typedef unsigned long long u64;

// scratch (allocation-free rule: __device__ globals)
__device__ __align__(16) float g_feats[NB * FEAT];
__device__ __align__(16) float g_head[NB * NROWS];

// packed dual-FMA: d.lo = a.lo*b.lo + c.lo ; d.hi = a.hi*b.hi + c.hi
__device__ __forceinline__ u64 ffma2(u64 a, u64 b, u64 c) {
    u64 d;
    asm("fma.rn.f32x2 %0, %1, %2, %3;" : "=l"(d) : "l"(a), "l"(b), "l"(c));
    return d;
}

__device__ __forceinline__ float sum2(u64 v) {
    union { u64 u; float f[2]; } cvt;
    cvt.u = v;
    return cvt.f[0] + cvt.f[1];
}

// default-cached (L1-resident) 16B load for feats
__device__ __forceinline__ ulonglong2 ldca128(const void* p) {
    ulonglong2 v;
    asm("ld.global.ca.v2.u64 {%0, %1}, [%2];"
        : "=l"(v.x), "=l"(v.y) : "l"(p));
    return v;
}

__device__ __forceinline__ unsigned smem_u32(const void* p) {
    return (unsigned)__cvta_generic_to_shared(p);
}

// bulk async copy global->shared::cta, completion counted on mbarrier
__device__ __forceinline__ void bulk_cp(unsigned dst, const void* src,
                                        unsigned bytes, unsigned mbar) {
    asm volatile(
        "cp.async.bulk.shared::cta.global.mbarrier::complete_tx::bytes "
        "[%0], [%1], %2, [%3];"
        :: "r"(dst), "l"(src), "r"(bytes), "r"(mbar) : "memory");
}

// ---------------------------------------------------------------------------
// Kernel A: build feats = [x_flat | triu(x x^T)] for all 8 batches.
// ---------------------------------------------------------------------------
__global__ void build_feats_kernel(const float* __restrict__ x) {
    __shared__ float xs[NB][IN_DIM];
    int tid = threadIdx.x;                       // 256 threads
    for (int t = tid; t < NB * IN_DIM; t += 256)
        xs[t >> 8][t & 255] = x[t];
    __syncthreads();

    int i = blockIdx.x;
    if (i < IN_DIM) {
        int j = tid;
        if (j >= i) {
            int off = IN_DIM + i * IN_DIM - (i * (i - 1)) / 2 + (j - i);
            #pragma unroll
            for (int b = 0; b < NB; b++)
                g_feats[b * FEAT + off] = xs[b][i] * xs[b][j];
        }
    } else {
        int j = tid;
        #pragma unroll
        for (int b = 0; b < NB; b++)
            g_feats[b * FEAT + j] = xs[b][j];
    }
}

// ---------------------------------------------------------------------------
// Kernel B: head_out[b][r] = dot(feats[b], W[r]) + bh[r]
//   W via 2-stage cp.async.bulk ring with 2 KB sequential burst per row per
//   bulk op (4x longer DRAM bursts than any prior variant). One mbarrier
//   wait per 4 compute iters. feats via L1 .ca. 1024 blocks x 64 thr, occ 7.
// ---------------------------------------------------------------------------
__global__ void __launch_bounds__(64, 7)
head_gemm_kernel(const float* __restrict__ W, const float* __restrict__ bh) {
    __shared__ __align__(128) float sw[2][8][KC];   // 32 KB
    __shared__ __align__(8)  u64  mbar[2];

    int tid  = threadIdx.x;
    int warp = tid >> 5;                 // 0..1
    int lane = tid & 31;
    int row0 = blockIdx.x * 8;

    const float* wbase = W + (size_t)row0 * FEAT;
    const float* fb    = g_feats + lane * 4;

    unsigned bar0 = smem_u32(&mbar[0]);
    unsigned bar1 = smem_u32(&mbar[1]);

    if (tid == 0) {
        asm volatile("mbarrier.init.shared.b64 [%0], 1;" :: "r"(bar0) : "memory");
        asm volatile("mbarrier.init.shared.b64 [%0], 1;" :: "r"(bar1) : "memory");
    }
    __syncthreads();

    // prologue: slots 0,1 <- chunks 0,1 (full 512-float chunks)
    if (tid == 0) {
        asm volatile("mbarrier.arrive.expect_tx.shared.b64 _, [%0], %1;"
                     :: "r"(bar0), "r"(8u * KC * 4u) : "memory");
        #pragma unroll
        for (int r = 0; r < 8; r++)
            bulk_cp(smem_u32(&sw[0][r][0]), wbase + (size_t)r * FEAT, KC * 4, bar0);
        asm volatile("mbarrier.arrive.expect_tx.shared.b64 _, [%0], %1;"
                     :: "r"(bar1), "r"(8u * KC * 4u) : "memory");
        #pragma unroll
        for (int r = 0; r < 8; r++)
            bulk_cp(smem_u32(&sw[1][r][0]), wbase + (size_t)r * FEAT + KC, KC * 4, bar1);
    }

    u64 acc[4][8];
    #pragma unroll
    for (int r = 0; r < 4; r++)
        #pragma unroll
        for (int b = 0; b < 8; b++) acc[r][b] = 0ull;

    #pragma unroll 1
    for (int c = 0; c < NCH; c++) {
        int slot = c & 1;
        unsigned bar = slot ? bar1 : bar0;
        unsigned ph  = (unsigned)((c >> 1) & 1);
        int len   = (c < NCH - 1) ? KC : (FEAT - (NCH - 1) * KC);   // 512 or 384
        int iters = len >> 7;                                        // 4 or 3

        // wait chunk ready (acquire)
        {
            unsigned done = 0;
            while (!done)
                asm volatile(
                    "{\n\t.reg .pred p;\n\t"
                    "mbarrier.try_wait.parity.acquire.cta.shared::cta.b64 p, [%1], %2, 0x989680;\n\t"
                    "selp.b32 %0, 1, 0, p;\n\t}"
                    : "=r"(done) : "r"(bar), "r"(ph) : "memory");
        }

        const float* fc = fb + c * KC;
        #pragma unroll 2
        for (int sub = 0; sub < iters; sub++) {
            int kl = sub * 128;
            const float* wrow = &sw[slot][warp * 4][kl + lane * 4];
            ulonglong2 a0 = *(const ulonglong2*)(wrow);
            ulonglong2 a1 = *(const ulonglong2*)(wrow + KC);
            ulonglong2 a2 = *(const ulonglong2*)(wrow + 2 * KC);
            ulonglong2 a3 = *(const ulonglong2*)(wrow + 3 * KC);

            const float* fk = fc + kl;
            #pragma unroll
            for (int b = 0; b < 8; b++) {
                ulonglong2 f = ldca128(fk + b * FEAT);
                acc[0][b] = ffma2(a0.x, f.x, acc[0][b]);
                acc[0][b] = ffma2(a0.y, f.y, acc[0][b]);
                acc[1][b] = ffma2(a1.x, f.x, acc[1][b]);
                acc[1][b] = ffma2(a1.y, f.y, acc[1][b]);
                acc[2][b] = ffma2(a2.x, f.x, acc[2][b]);
                acc[2][b] = ffma2(a2.y, f.y, acc[2][b]);
                acc[3][b] = ffma2(a3.x, f.x, acc[3][b]);
                acc[3][b] = ffma2(a3.y, f.y, acc[3][b]);
            }
        }

        __syncthreads();   // whole block done with this slot

        int nc = c + 2;    // refill this slot with chunk c+2
        if (nc < NCH && tid == 0) {
            unsigned nlen  = (nc < NCH - 1) ? (KC * 4u) : (unsigned)((FEAT - (NCH - 1) * KC) * 4);
            asm volatile("mbarrier.arrive.expect_tx.shared.b64 _, [%0], %1;"
                         :: "r"(bar), "r"(8u * nlen) : "memory");
            #pragma unroll
            for (int r = 0; r < 8; r++)
                bulk_cp(smem_u32(&sw[slot][r][0]),
                        wbase + (size_t)r * FEAT + (size_t)nc * KC, nlen, bar);
        }
    }

    int rbase = warp * 4;
    #pragma unroll
    for (int r = 0; r < 4; r++) {
        #pragma unroll
        for (int b = 0; b < 8; b++) {
            float v = sum2(acc[r][b]);
            #pragma unroll
            for (int o = 16; o > 0; o >>= 1)
                v += __shfl_xor_sync(0xffffffffu, v, o);
            if (lane == 0)
                g_head[b * NROWS + row0 + rbase + r] = v + bh[row0 + rbase + r];
        }
    }
}

// ---------------------------------------------------------------------------
// Kernel C: out[b][s][o] = dot(concat[b][s], W_out[o]) + b_out[o]
// ---------------------------------------------------------------------------
__global__ void out_gemm_kernel(const float* __restrict__ Wout,
                                const float* __restrict__ bout,
                                float* __restrict__ out) {
    __shared__ float cs[256];
    int bs = blockIdx.x;
    int b  = bs >> 5;
    int s  = bs & 31;
    int t  = threadIdx.x;    // 64 threads

    #pragma unroll
    for (int q = 0; q < 4; q++) {
        int j = t + q * 64;
        cs[j] = g_head[b * NROWS + (j >> 6) * 2048 + s * 64 + (j & 63)];
    }
    __syncthreads();

    const float* wr = Wout + t * 256;
    float sum = bout[t];
    #pragma unroll
    for (int j = 0; j < 256; j += 4) {
        float4 w = *(const float4*)(wr + j);
        sum = fmaf(w.x, cs[j],
              fmaf(w.y, cs[j + 1],
              fmaf(w.z, cs[j + 2],
              fmaf(w.w, cs[j + 3], sum))));
    }
    out[bs * 64 + t] = sum;
}

// ---------------------------------------------------------------------------
extern "C" void kernel_launch(void* const* d_in, const int* in_sizes, int n_in,
                              void* d_out, int out_size) {
    const float* x   = (const float*)d_in[0];   // (8,32,8)
    const float* W   = (const float*)d_in[1];   // (4,2048,33152)
    const float* bh  = (const float*)d_in[2];   // (4,2048)
    const float* Wo  = (const float*)d_in[3];   // (64,256)
    const float* bo  = (const float*)d_in[4];   // (64,)
    float* out = (float*)d_out;                 // (8,32,64)

    // make sure the 224 KB/SM smem carveout is available for occupancy 7
    static int carveout_done = 0;
    (void)carveout_done;  // attribute call is idempotent & cheap; do it every call
    cudaFuncSetAttribute(head_gemm_kernel,
                         cudaFuncAttributePreferredSharedMemoryCarveout, 100);

    build_feats_kernel<<<IN_DIM + 1, 256>>>(x);
    head_gemm_kernel<<<NROWS / 8, 64>>>(W, bh);
    out_gemm_kernel<<<256, 64>>>(Wo, bo, out);
}

// round 10
// speedup vs baseline: 2.6056x; 2.6056x over previous
#include <cuda_runtime.h>

#define IN_DIM 256
#define FEAT   33152      // 256 + (256 + 256*256)/2 = 518 * 64
#define NB     8          // batch
#define NROWS  8192       // NHEAD * S * D_MODEL
#define KITERS 518        // FEAT / 64, exact
#define OUTF   64

typedef unsigned long long u64;

// scratch (allocation-free rule: __device__ globals)
__device__ __align__(16) float g_feats[NB * FEAT];
__device__ __align__(16) float g_head[NB * NROWS];

// packed dual-FMA: d.lo = a.lo*b.lo + c.lo ; d.hi = a.hi*b.hi + c.hi
__device__ __forceinline__ u64 ffma2(u64 a, u64 b, u64 c) {
    u64 d;
    asm("fma.rn.f32x2 %0, %1, %2, %3;" : "=l"(d) : "l"(a), "l"(b), "l"(c));
    return d;
}

__device__ __forceinline__ float sum2(u64 v) {
    union { u64 u; float f[2]; } cvt;
    cvt.u = v;
    return cvt.f[0] + cvt.f[1];
}

// L1-cached 8-byte load (k-pair)
__device__ __forceinline__ u64 ldca64(const void* p) {
    u64 v;
    asm("ld.global.ca.u64 %0, [%1];" : "=l"(v) : "l"(p));
    return v;
}

// ---------------------------------------------------------------------------
// Kernel A: build feats = [x_flat | triu(x x^T)] for all 8 batches.
// ---------------------------------------------------------------------------
__global__ void build_feats_kernel(const float* __restrict__ x) {
    __shared__ float xs[NB][IN_DIM];
    int tid = threadIdx.x;                       // 256 threads
    for (int t = tid; t < NB * IN_DIM; t += 256)
        xs[t >> 8][t & 255] = x[t];
    __syncthreads();

    int i = blockIdx.x;
    if (i < IN_DIM) {
        int j = tid;
        if (j >= i) {
            int off = IN_DIM + i * IN_DIM - (i * (i - 1)) / 2 + (j - i);
            #pragma unroll
            for (int b = 0; b < NB; b++)
                g_feats[b * FEAT + off] = xs[b][i] * xs[b][j];
        }
    } else {
        int j = tid;
        #pragma unroll
        for (int b = 0; b < NB; b++)
            g_feats[b * FEAT + j] = xs[b][j];
    }
}

// ---------------------------------------------------------------------------
// Kernel B: head_out[b][r] = dot(feats[b], W[r]) + bh[r]
//   Issue-lean consumer: warp = 8 rows x 4 batches, 2 k per lane (LDG.64).
//   Per 2048 B of W: 32 FFMA2 + 12 LDG.64 (~117 SMSP-cyc -> drain ~70 B/cyc/SM,
//   2.3x DRAM need). W reuse x2 in-block (warp0 b0-3, warp1 b4-7, same rows),
//   W via L1 .ca so the follower warp hits L1. 1024 blocks x 64 thr, occ 8.
// ---------------------------------------------------------------------------
__global__ void __launch_bounds__(64, 8)
head_gemm_kernel(const float* __restrict__ W, const float* __restrict__ bh) {
    int warp = threadIdx.x >> 5;                 // 0..1 -> batch half
    int lane = threadIdx.x & 31;
    int row0 = blockIdx.x * 8;
    int bb   = warp * 4;                         // batch base

    const float* wp = W + (size_t)row0 * FEAT + lane * 2;
    const float* fp = g_feats + (size_t)bb * FEAT + lane * 2;

    u64 acc[8][4];
    #pragma unroll
    for (int r = 0; r < 8; r++)
        #pragma unroll
        for (int b = 0; b < 4; b++) acc[r][b] = 0ull;

    #pragma unroll 2
    for (int it = 0; it < KITERS; it++) {
        // 8 W row-slices (8 B each), all at immediate offsets off one pointer
        u64 a0 = ldca64(wp + 0 * FEAT);
        u64 a1 = ldca64(wp + 1 * FEAT);
        u64 a2 = ldca64(wp + 2 * FEAT);
        u64 a3 = ldca64(wp + 3 * FEAT);
        u64 a4 = ldca64(wp + 4 * FEAT);
        u64 a5 = ldca64(wp + 5 * FEAT);
        u64 a6 = ldca64(wp + 6 * FEAT);
        u64 a7 = ldca64(wp + 7 * FEAT);
        // 4 feats slices (this warp's batch half)
        u64 f0 = ldca64(fp + 0 * FEAT);
        u64 f1 = ldca64(fp + 1 * FEAT);
        u64 f2 = ldca64(fp + 2 * FEAT);
        u64 f3 = ldca64(fp + 3 * FEAT);

        acc[0][0] = ffma2(a0, f0, acc[0][0]);
        acc[0][1] = ffma2(a0, f1, acc[0][1]);
        acc[0][2] = ffma2(a0, f2, acc[0][2]);
        acc[0][3] = ffma2(a0, f3, acc[0][3]);
        acc[1][0] = ffma2(a1, f0, acc[1][0]);
        acc[1][1] = ffma2(a1, f1, acc[1][1]);
        acc[1][2] = ffma2(a1, f2, acc[1][2]);
        acc[1][3] = ffma2(a1, f3, acc[1][3]);
        acc[2][0] = ffma2(a2, f0, acc[2][0]);
        acc[2][1] = ffma2(a2, f1, acc[2][1]);
        acc[2][2] = ffma2(a2, f2, acc[2][2]);
        acc[2][3] = ffma2(a2, f3, acc[2][3]);
        acc[3][0] = ffma2(a3, f0, acc[3][0]);
        acc[3][1] = ffma2(a3, f1, acc[3][1]);
        acc[3][2] = ffma2(a3, f2, acc[3][2]);
        acc[3][3] = ffma2(a3, f3, acc[3][3]);
        acc[4][0] = ffma2(a4, f0, acc[4][0]);
        acc[4][1] = ffma2(a4, f1, acc[4][1]);
        acc[4][2] = ffma2(a4, f2, acc[4][2]);
        acc[4][3] = ffma2(a4, f3, acc[4][3]);
        acc[5][0] = ffma2(a5, f0, acc[5][0]);
        acc[5][1] = ffma2(a5, f1, acc[5][1]);
        acc[5][2] = ffma2(a5, f2, acc[5][2]);
        acc[5][3] = ffma2(a5, f3, acc[5][3]);
        acc[6][0] = ffma2(a6, f0, acc[6][0]);
        acc[6][1] = ffma2(a6, f1, acc[6][1]);
        acc[6][2] = ffma2(a6, f2, acc[6][2]);
        acc[6][3] = ffma2(a6, f3, acc[6][3]);
        acc[7][0] = ffma2(a7, f0, acc[7][0]);
        acc[7][1] = ffma2(a7, f1, acc[7][1]);
        acc[7][2] = ffma2(a7, f2, acc[7][2]);
        acc[7][3] = ffma2(a7, f3, acc[7][3]);

        wp += 64;
        fp += 64;
    }

    // fold k-parity halves, warp-reduce, write (32 results per warp)
    #pragma unroll
    for (int r = 0; r < 8; r++) {
        #pragma unroll
        for (int b = 0; b < 4; b++) {
            float v = sum2(acc[r][b]);
            #pragma unroll
            for (int o = 16; o > 0; o >>= 1)
                v += __shfl_xor_sync(0xffffffffu, v, o);
            if (lane == 0)
                g_head[(bb + b) * NROWS + row0 + r] = v + bh[row0 + r];
        }
    }
}

// ---------------------------------------------------------------------------
// Kernel C: out[b][s][o] = dot(concat[b][s], W_out[o]) + b_out[o]
// ---------------------------------------------------------------------------
__global__ void out_gemm_kernel(const float* __restrict__ Wout,
                                const float* __restrict__ bout,
                                float* __restrict__ out) {
    __shared__ float cs[256];
    int bs = blockIdx.x;
    int b  = bs >> 5;
    int s  = bs & 31;
    int t  = threadIdx.x;    // 64 threads

    #pragma unroll
    for (int q = 0; q < 4; q++) {
        int j = t + q * 64;
        cs[j] = g_head[b * NROWS + (j >> 6) * 2048 + s * 64 + (j & 63)];
    }
    __syncthreads();

    const float* wr = Wout + t * 256;
    float sum = bout[t];
    #pragma unroll
    for (int j = 0; j < 256; j += 4) {
        float4 w = *(const float4*)(wr + j);
        sum = fmaf(w.x, cs[j],
              fmaf(w.y, cs[j + 1],
              fmaf(w.z, cs[j + 2],
              fmaf(w.w, cs[j + 3], sum))));
    }
    out[bs * 64 + t] = sum;
}

// ---------------------------------------------------------------------------
extern "C" void kernel_launch(void* const* d_in, const int* in_sizes, int n_in,
                              void* d_out, int out_size) {
    const float* x   = (const float*)d_in[0];   // (8,32,8)
    const float* W   = (const float*)d_in[1];   // (4,2048,33152)
    const float* bh  = (const float*)d_in[2];   // (4,2048)
    const float* Wo  = (const float*)d_in[3];   // (64,256)
    const float* bo  = (const float*)d_in[4];   // (64,)
    float* out = (float*)d_out;                 // (8,32,64)

    build_feats_kernel<<<IN_DIM + 1, 256>>>(x);
    head_gemm_kernel<<<NROWS / 8, 64>>>(W, bh);
    out_gemm_kernel<<<256, 64>>>(Wo, bo, out);
}